// round 13
// baseline (speedup 1.0000x reference)
#include <cuda_runtime.h>
#include <cuda_bf16.h>
#include <cstdint>

// ---------------- problem constants ----------------
#define N_TOT 8192
#define D     128
#define IPC_C 512
#define ROW0  7680            // bz - IPC
#define NCOL  7680            // unmasked columns [0, 7680)
#define BM    128
#define BN    256
#define NTIL  (NCOL / BN)     // 30 column tiles
#define ETIL  (1024 / BN)     // tiles [0,4) = easy region (exact boundary)
#define NBLK  (NTIL * (IPC_C / BM))   // 120 blocks = one wave (1 block/SM)
#define LDB   136             // bf16 smem row stride; 68 uint32

// ---------------- device globals ----------------
__device__ float g_inv[N_TOT];            // inverse norms
__device__ float g_part[NTIL * IPC_C];    // [colTile][row] partial maxima
__device__ int   g_sync;                  // phase-0 barrier; reset each replay
__device__ int   g_done;                  // finalize counter; reset each replay

// smem: A bf16[128][136] + B bf16[256][136] = 104448 B
#define SMEM_BYTES (BM * LDB * 2 + BN * LDB * 2)

__global__ void __launch_bounds__(512, 1) hse_kernel(const float* __restrict__ fvec,
                                                     const float* __restrict__ a_scl,
                                                     float* __restrict__ out) {
    extern __shared__ char smraw[];
    __nv_bfloat16* As = (__nv_bfloat16*)smraw;
    __nv_bfloat16* Bs = As + BM * LDB;

    const int tid  = threadIdx.x;
    const int lane = tid & 31;
    const int w    = tid >> 5;
    const int wm   = w >> 2;        // 0..3 -> 32-row strip
    const int wn   = w & 3;         // 0..3 -> 64-col strip
    const int q    = lane >> 2;     // 0..7
    const int tig  = lane & 3;      // 0..3
    const int bid  = blockIdx.x;
    const int rowBase = ROW0 + (bid / NTIL) * BM;
    const int colBase = (bid % NTIL) * BN;

    // ================= phase 0: inverse norms for strided row slice =================
    // rows {bid + 120*i}, i in [0,128). All lanes execute the shfl (row clamped);
    // only in-range rows are written -> no divergent collective, no deadlock.
    #pragma unroll
    for (int p = 0; p < 2; p++) {
        int i    = p * 64 + (tid >> 3);
        int row  = bid + NBLK * i;
        int rowc = row < N_TOT ? row : N_TOT - 1;   // uniform-compute clamp
        const int l8 = tid & 7;
        const float4* src = (const float4*)(fvec + (size_t)rowc * D);
        float s = 0.f;
        #pragma unroll
        for (int j = 0; j < 4; j++) {
            float4 v = src[l8 + 8 * j];
            s += v.x * v.x + v.y * v.y + v.z * v.z + v.w * v.w;
        }
        #pragma unroll
        for (int o = 1; o < 8; o <<= 1) s += __shfl_xor_sync(0xffffffffu, s, o);
        if (l8 == 0 && row < N_TOT) {
            float inv = rsqrtf(s);
            if (!(s > 1e-24f)) inv = 1e12f;
            g_inv[row] = inv;
        }
    }

    // ---- grid-wide barrier (all 120 blocks resident -> deadlock-free) ----
    __threadfence();
    __syncthreads();
    if (tid == 0) {
        atomicAdd(&g_sync, 1);
        while (*(volatile int*)&g_sync < NBLK) { }
        __threadfence();
    }
    __syncthreads();

    // ================= phase 1: stage + normalize + cvt bf16 =================
    #pragma unroll
    for (int t = 0; t < 8; t++) {
        int idx = tid + t * 512;
        int r = idx >> 5, c4 = idx & 31;
        int gr = rowBase + r;
        float4 v = __ldg((const float4*)(fvec + (size_t)gr * D) + c4);
        float inv = __ldg(g_inv + gr);
        __nv_bfloat162 p0 = __floats2bfloat162_rn(v.x * inv, v.y * inv);
        __nv_bfloat162 p1 = __floats2bfloat162_rn(v.z * inv, v.w * inv);
        *(uint2*)(As + r * LDB + c4 * 4) = make_uint2(*(uint32_t*)&p0, *(uint32_t*)&p1);
    }
    #pragma unroll
    for (int t = 0; t < 16; t++) {
        int idx = tid + t * 512;
        int r = idx >> 5, c4 = idx & 31;
        int gr = colBase + r;
        float4 v = __ldg((const float4*)(fvec + (size_t)gr * D) + c4);
        float inv = __ldg(g_inv + gr);
        __nv_bfloat162 p0 = __floats2bfloat162_rn(v.x * inv, v.y * inv);
        __nv_bfloat162 p1 = __floats2bfloat162_rn(v.z * inv, v.w * inv);
        *(uint2*)(Bs + r * LDB + c4 * 4) = make_uint2(*(uint32_t*)&p0, *(uint32_t*)&p1);
    }
    __syncthreads();

    // ================= phase 2: R8 mainloop =================
    float acc[2][8][4];
    #pragma unroll
    for (int mt = 0; mt < 2; mt++)
        #pragma unroll
        for (int nt = 0; nt < 8; nt++)
            #pragma unroll
            for (int e = 0; e < 4; e++) acc[mt][nt][e] = 0.f;

    const uint32_t* A32 = (const uint32_t*)As;   // row*68 + kpair
    const uint32_t* B32 = (const uint32_t*)Bs;
    const int rA0 = wm * 32 + q;
    const int rB0 = wn * 64 + q;

    #pragma unroll
    for (int s = 0; s < 8; s++) {            // 8 K-steps of k16
        const int ko = s * 8 + tig;
        uint32_t af[2][4];
        #pragma unroll
        for (int mt = 0; mt < 2; mt++) {
            int b0 = (rA0 + mt * 16) * 68 + ko;
            af[mt][0] = A32[b0];
            af[mt][1] = A32[b0 + 8 * 68];
            af[mt][2] = A32[b0 + 4];
            af[mt][3] = A32[b0 + 8 * 68 + 4];
        }
        uint32_t bf[8][2];
        #pragma unroll
        for (int nt = 0; nt < 8; nt++) {
            int b0 = (rB0 + nt * 8) * 68 + ko;
            bf[nt][0] = B32[b0];
            bf[nt][1] = B32[b0 + 4];
        }
        #pragma unroll
        for (int mt = 0; mt < 2; mt++)
            #pragma unroll
            for (int nt = 0; nt < 8; nt++)
                asm volatile(
                    "mma.sync.aligned.m16n8k16.row.col.f32.bf16.bf16.f32 "
                    "{%0,%1,%2,%3}, {%4,%5,%6,%7}, {%8,%9}, {%0,%1,%2,%3};"
                    : "+f"(acc[mt][nt][0]), "+f"(acc[mt][nt][1]),
                      "+f"(acc[mt][nt][2]), "+f"(acc[mt][nt][3])
                    : "r"(af[mt][0]), "r"(af[mt][1]), "r"(af[mt][2]), "r"(af[mt][3]),
                      "r"(bf[nt][0]), "r"(bf[nt][1]));
    }
    __syncthreads();   // all smem reads done before reuse

    // ================= phase 3: row max -> g_part =================
    float* pm = (float*)smraw;    // [4(wn)][128]
    #pragma unroll
    for (int mt = 0; mt < 2; mt++) {
        float mlo = -2.f, mhi = -2.f;
        #pragma unroll
        for (int nt = 0; nt < 8; nt++) {
            mlo = fmaxf(mlo, fmaxf(acc[mt][nt][0], acc[mt][nt][1]));
            mhi = fmaxf(mhi, fmaxf(acc[mt][nt][2], acc[mt][nt][3]));
        }
        #pragma unroll
        for (int o = 1; o < 4; o <<= 1) {
            mlo = fmaxf(mlo, __shfl_xor_sync(0xffffffffu, mlo, o));
            mhi = fmaxf(mhi, __shfl_xor_sync(0xffffffffu, mhi, o));
        }
        if (tig == 0) {
            int r = wm * 32 + mt * 16 + q;
            pm[wn * 128 + r]     = mlo;
            pm[wn * 128 + r + 8] = mhi;
        }
    }
    __syncthreads();

    if (tid < BM) {
        float m = fmaxf(fmaxf(pm[tid], pm[128 + tid]),
                        fmaxf(pm[256 + tid], pm[384 + tid]));
        g_part[(bid % NTIL) * IPC_C + (bid / NTIL) * BM + tid] = m;
    }
    __syncthreads();

    // ================= phase 4: last-block finalize =================
    __shared__ int isLast;
    __shared__ float sred;
    if (tid == 0) {
        __threadfence();
        isLast = (atomicAdd(&g_done, 1) == NBLK - 1);
    }
    __syncthreads();
    if (!isLast) return;

    if (tid == 0) { __threadfence(); sred = 0.f; }
    __syncthreads();

    float e = -2.f, h = -2.f;
    #pragma unroll
    for (int j = 0; j < ETIL; j++)     e = fmaxf(e, g_part[j * IPC_C + tid]);
    #pragma unroll
    for (int j = ETIL; j < NTIL; j++)  h = fmaxf(h, g_part[j * IPC_C + tid]);
    float loss = log1pf(expf((h - e) * 10.0f));   // 1/SIGMA1 = 10
    #pragma unroll
    for (int o = 16; o; o >>= 1) loss += __shfl_xor_sync(0xffffffffu, loss, o);
    if (lane == 0) atomicAdd(&sred, loss);
    __syncthreads();

    if (tid == 0) {
        out[0] = a_scl[0] * sred * (1.0f / 512.0f);
        g_done = 0;      // reset for the next graph replay
        g_sync = 0;
    }
}

extern "C" void kernel_launch(void* const* d_in, const int* in_sizes, int n_in,
                              void* d_out, int out_size) {
    const float* fvec = (const float*)d_in[0];   // [8192,128] f32
    // d_in[1] = Lvec (dead in the reference math)
    const float* a    = (const float*)d_in[2];   // scalar f32
    float* out = (float*)d_out;

    cudaFuncSetAttribute(hse_kernel,
                         cudaFuncAttributeMaxDynamicSharedMemorySize, SMEM_BYTES);

    hse_kernel<<<NBLK, 512, SMEM_BYTES>>>(fvec, a, out);
}

// round 14
// speedup vs baseline: 1.0022x; 1.0022x over previous
#include <cuda_runtime.h>
#include <cuda_bf16.h>
#include <cstdint>

// ---------------- problem constants ----------------
#define N_TOT 8192
#define D     128
#define IPC_C 512
#define ROW0  7680            // bz - IPC
#define NCOL  7680            // unmasked columns [0, 7680)
#define BM    128
#define BN    256
#define NTIL  (NCOL / BN)     // 30 column tiles
#define ETIL  (1024 / BN)     // tiles [0,4) = easy region (exact boundary)
#define NBLK  (NTIL * (IPC_C / BM))   // 120 blocks = one wave
#define LDB   136             // bf16 smem row stride; 68 uint32

// ---------------- device globals ----------------
__device__ float g_invr[IPC_C];           // inverse norms of the 512 rows
__device__ float g_part[NTIL * IPC_C];    // [colTile][row] partial (col-scaled) maxima
__device__ int   g_done;                  // zero-init; reset each replay

// smem: A bf16[128][136] + B bf16[256][136] + invB float[256]
#define OFF_INVB (BM * LDB * 2 + BN * LDB * 2)
#define SMEM_BYTES (OFF_INVB + BN * 4)

__global__ void __launch_bounds__(512, 1) hse_kernel(const float* __restrict__ fvec,
                                                     const float* __restrict__ a_scl,
                                                     float* __restrict__ out) {
    extern __shared__ char smraw[];
    __nv_bfloat16* As = (__nv_bfloat16*)smraw;
    __nv_bfloat16* Bs = As + BM * LDB;
    float* invB = (float*)(smraw + OFF_INVB);

    const int tid  = threadIdx.x;
    const int lane = tid & 31;
    const int w    = tid >> 5;
    const int wm   = w >> 2;        // 0..3 -> 32-row strip
    const int wn   = w & 3;         // 0..3 -> 64-col strip
    const int q    = lane >> 2;     // 0..7
    const int tig  = lane & 3;      // 0..3
    const int bid  = blockIdx.x;
    const int rowBase = ROW0 + (bid / NTIL) * BM;
    const int colBase = (bid % NTIL) * BN;

    // ---- stage A raw->bf16; warp w loads row w+16t, norm via shfl ----
    #pragma unroll
    for (int t = 0; t < 8; t++) {
        int r = w + t * 16;                  // warp-uniform
        int gr = rowBase + r;
        float4 v = __ldg((const float4*)(fvec + (size_t)gr * D) + lane);
        float ss = v.x * v.x + v.y * v.y + v.z * v.z + v.w * v.w;
        #pragma unroll
        for (int o = 1; o < 32; o <<= 1) ss += __shfl_xor_sync(0xffffffffu, ss, o);
        if (lane == 0) {
            float inv = rsqrtf(ss);
            if (!(ss > 1e-24f)) inv = 1e12f;
            g_invr[(bid / NTIL) * BM + r] = inv;   // duplicate writes across col tiles: benign
        }
        __nv_bfloat162 p0 = __floats2bfloat162_rn(v.x, v.y);
        __nv_bfloat162 p1 = __floats2bfloat162_rn(v.z, v.w);
        *(uint2*)(As + r * LDB + lane * 4) = make_uint2(*(uint32_t*)&p0, *(uint32_t*)&p1);
    }
    // ---- stage B raw->bf16; inv norms into smem ----
    #pragma unroll
    for (int t = 0; t < 16; t++) {
        int r = w + t * 16;                  // warp-uniform
        int gr = colBase + r;
        float4 v = __ldg((const float4*)(fvec + (size_t)gr * D) + lane);
        float ss = v.x * v.x + v.y * v.y + v.z * v.z + v.w * v.w;
        #pragma unroll
        for (int o = 1; o < 32; o <<= 1) ss += __shfl_xor_sync(0xffffffffu, ss, o);
        if (lane == 0) {
            float inv = rsqrtf(ss);
            if (!(ss > 1e-24f)) inv = 1e12f;
            invB[r] = inv;
        }
        __nv_bfloat162 p0 = __floats2bfloat162_rn(v.x, v.y);
        __nv_bfloat162 p1 = __floats2bfloat162_rn(v.z, v.w);
        *(uint2*)(Bs + r * LDB + lane * 4) = make_uint2(*(uint32_t*)&p0, *(uint32_t*)&p1);
    }
    __syncthreads();

    // ---- mainloop: 8 K-steps of m16n8k16 bf16 (proven R8 core) ----
    float acc[2][8][4];
    #pragma unroll
    for (int mt = 0; mt < 2; mt++)
        #pragma unroll
        for (int nt = 0; nt < 8; nt++)
            #pragma unroll
            for (int e = 0; e < 4; e++) acc[mt][nt][e] = 0.f;

    const uint32_t* A32 = (const uint32_t*)As;   // row*68 + kpair
    const uint32_t* B32 = (const uint32_t*)Bs;
    const int rA0 = wm * 32 + q;
    const int rB0 = wn * 64 + q;

    #pragma unroll
    for (int s = 0; s < 8; s++) {
        const int ko = s * 8 + tig;
        uint32_t af[2][4];
        #pragma unroll
        for (int mt = 0; mt < 2; mt++) {
            int b0 = (rA0 + mt * 16) * 68 + ko;
            af[mt][0] = A32[b0];
            af[mt][1] = A32[b0 + 8 * 68];
            af[mt][2] = A32[b0 + 4];
            af[mt][3] = A32[b0 + 8 * 68 + 4];
        }
        uint32_t bf[8][2];
        #pragma unroll
        for (int nt = 0; nt < 8; nt++) {
            int b0 = (rB0 + nt * 8) * 68 + ko;
            bf[nt][0] = B32[b0];
            bf[nt][1] = B32[b0 + 4];
        }
        #pragma unroll
        for (int mt = 0; mt < 2; mt++)
            #pragma unroll
            for (int nt = 0; nt < 8; nt++)
                asm volatile(
                    "mma.sync.aligned.m16n8k16.row.col.f32.bf16.bf16.f32 "
                    "{%0,%1,%2,%3}, {%4,%5,%6,%7}, {%8,%9}, {%0,%1,%2,%3};"
                    : "+f"(acc[mt][nt][0]), "+f"(acc[mt][nt][1]),
                      "+f"(acc[mt][nt][2]), "+f"(acc[mt][nt][3])
                    : "r"(af[mt][0]), "r"(af[mt][1]), "r"(af[mt][2]), "r"(af[mt][3]),
                      "r"(bf[nt][0]), "r"(bf[nt][1]));
    }
    __syncthreads();   // all As/Bs reads done before pm overwrites As

    // ---- epilogue: scale by column inv-norm, then row max ----
    float* pm = (float*)smraw;    // [4(wn)][128]  (overlaps As only)
    #pragma unroll
    for (int mt = 0; mt < 2; mt++) {
        float mlo = -1e30f, mhi = -1e30f;
        #pragma unroll
        for (int nt = 0; nt < 8; nt++) {
            float2 ic = *(const float2*)(invB + wn * 64 + nt * 8 + tig * 2);
            mlo = fmaxf(mlo, fmaxf(acc[mt][nt][0] * ic.x, acc[mt][nt][1] * ic.y));
            mhi = fmaxf(mhi, fmaxf(acc[mt][nt][2] * ic.x, acc[mt][nt][3] * ic.y));
        }
        #pragma unroll
        for (int o = 1; o < 4; o <<= 1) {
            mlo = fmaxf(mlo, __shfl_xor_sync(0xffffffffu, mlo, o));
            mhi = fmaxf(mhi, __shfl_xor_sync(0xffffffffu, mhi, o));
        }
        if (tig == 0) {
            int r = wm * 32 + mt * 16 + q;
            pm[wn * 128 + r]     = mlo;
            pm[wn * 128 + r + 8] = mhi;
        }
    }
    __syncthreads();

    if (tid < BM) {
        float m = fmaxf(fmaxf(pm[tid], pm[128 + tid]),
                        fmaxf(pm[256 + tid], pm[384 + tid]));
        g_part[(bid % NTIL) * IPC_C + (bid / NTIL) * BM + tid] = m;
    }
    __syncthreads();

    // ---- last-block-done fused finalize ----
    __shared__ int isLast;
    __shared__ float sred;
    if (tid == 0) {
        __threadfence();
        isLast = (atomicAdd(&g_done, 1) == NBLK - 1);
    }
    __syncthreads();
    if (!isLast) return;

    if (tid == 0) { __threadfence(); sred = 0.f; }
    __syncthreads();

    float e = -1e30f, h = -1e30f;
    #pragma unroll
    for (int j = 0; j < ETIL; j++)     e = fmaxf(e, g_part[j * IPC_C + tid]);
    #pragma unroll
    for (int j = ETIL; j < NTIL; j++)  h = fmaxf(h, g_part[j * IPC_C + tid]);
    float loss = log1pf(expf((h - e) * 10.0f * g_invr[tid]));   // 1/SIGMA1 = 10
    #pragma unroll
    for (int o = 16; o; o >>= 1) loss += __shfl_xor_sync(0xffffffffu, loss, o);
    if (lane == 0) atomicAdd(&sred, loss);
    __syncthreads();

    if (tid == 0) {
        out[0] = a_scl[0] * sred * (1.0f / 512.0f);
        g_done = 0;      // reset for the next graph replay
    }
}

extern "C" void kernel_launch(void* const* d_in, const int* in_sizes, int n_in,
                              void* d_out, int out_size) {
    const float* fvec = (const float*)d_in[0];   // [8192,128] f32
    // d_in[1] = Lvec (dead in the reference math)
    const float* a    = (const float*)d_in[2];   // scalar f32
    float* out = (float*)d_out;

    cudaFuncSetAttribute(hse_kernel,
                         cudaFuncAttributeMaxDynamicSharedMemorySize, SMEM_BYTES);

    hse_kernel<<<NBLK, 512, SMEM_BYTES>>>(fvec, a, out);
}